// round 2
// baseline (speedup 1.0000x reference)
#include <cuda_runtime.h>
#include <cstdint>

// MeanAggregator: out[b, :] = (1/S) * sum_{s<S} features[neigh_idx[b,s], :]
// B=50000, S=10, N=1e6, D=128 (fp32). neigh_idx is INT32 (JAX x64 disabled).
// One warp per output node; each lane owns a float4 slice of D.

#define D_DIM 128

template<int S>
__global__ __launch_bounds__(256, 8)
void mean_agg_kernel(const int* __restrict__ neigh_idx,
                     const float* __restrict__ features,
                     float* __restrict__ out,
                     int B, float inv_s)
{
    int warp = (blockIdx.x * blockDim.x + threadIdx.x) >> 5;
    int lane = threadIdx.x & 31;
    if (warp >= B) return;

    const int* __restrict__ idx_row = neigh_idx + (long long)warp * S;

    // Load all S row indices first (uniform across warp — L1 broadcast).
    int rows[S];
#pragma unroll
    for (int s = 0; s < S; s++) rows[s] = idx_row[s];

    // Issue all S gathers back-to-back for max MLP.
    float4 v[S];
#pragma unroll
    for (int s = 0; s < S; s++) {
        const float4* p = reinterpret_cast<const float4*>(
            features + (long long)rows[s] * D_DIM) + lane;
        v[s] = __ldg(p);
    }

    float4 acc = make_float4(0.f, 0.f, 0.f, 0.f);
#pragma unroll
    for (int s = 0; s < S; s++) {
        acc.x += v[s].x; acc.y += v[s].y; acc.z += v[s].z; acc.w += v[s].w;
    }
    acc.x *= inv_s; acc.y *= inv_s; acc.z *= inv_s; acc.w *= inv_s;

    float4* o = reinterpret_cast<float4*>(out + (long long)warp * D_DIM) + lane;
    *o = acc;
}

// Generic fallback (S not known at compile time).
__global__ __launch_bounds__(256, 8)
void mean_agg_kernel_dyn(const int* __restrict__ neigh_idx,
                         const float* __restrict__ features,
                         float* __restrict__ out,
                         int B, int S, float inv_s)
{
    int warp = (blockIdx.x * blockDim.x + threadIdx.x) >> 5;
    int lane = threadIdx.x & 31;
    if (warp >= B) return;

    const int* __restrict__ idx_row = neigh_idx + (long long)warp * S;
    float4 acc = make_float4(0.f, 0.f, 0.f, 0.f);
    for (int s = 0; s < S; s++) {
        int r = idx_row[s];
        float4 vv = __ldg(reinterpret_cast<const float4*>(
            features + (long long)r * D_DIM) + lane);
        acc.x += vv.x; acc.y += vv.y; acc.z += vv.z; acc.w += vv.w;
    }
    acc.x *= inv_s; acc.y *= inv_s; acc.z *= inv_s; acc.w *= inv_s;
    float4* o = reinterpret_cast<float4*>(out + (long long)warp * D_DIM) + lane;
    *o = acc;
}

extern "C" void kernel_launch(void* const* d_in, const int* in_sizes, int n_in,
                              void* d_out, int out_size)
{
    const int*   neigh_idx = (const int*)d_in[0];   // [B, S] int32
    const float* features  = (const float*)d_in[1]; // [N, D] fp32
    // d_in[2] = num_sample scalar — unused; derive S from sizes.

    int B = out_size / D_DIM;          // out is [B, 128]
    int S = in_sizes[0] / B;           // neigh_idx is [B, S]
    float inv_s = 1.0f / (float)S;

    float* out = (float*)d_out;

    int warps_per_block = 256 / 32;
    int grid = (B + warps_per_block - 1) / warps_per_block;

    if (S == 10) {
        mean_agg_kernel<10><<<grid, 256>>>(neigh_idx, features, out, B, inv_s);
    } else {
        mean_agg_kernel_dyn<<<grid, 256>>>(neigh_idx, features, out, B, S, inv_s);
    }
}